// round 4
// baseline (speedup 1.0000x reference)
#include <cuda_runtime.h>
#include <math.h>

// Problem constants: N=100000, E=1600000, F_IN=256, F_OUT=40
#define N_MAX 100000
#define E_MAX 1600000
#define F_IN  256
#define F_OUT 40
#define F4    (F_OUT / 4)   // 10 float4 chunks per node row
#define SCAN_BS 1024
#define SCAN_NB ((N_MAX + SCAN_BS - 1) / SCAN_BS)   // 98

// Scratch in __device__ globals (no allocation allowed in kernel_launch).
__device__ int    g_is64;
__device__ float  g_deg [N_MAX];
__device__ float  g_dinv[N_MAX];
__device__ int    g_rowi[E_MAX];       // decoded int32 row
__device__ int    g_coli[E_MAX];       // decoded int32 col
__device__ int    g_cnt [N_MAX];       // histogram of col
__device__ int    g_cur [N_MAX];       // bucket cursors
__device__ int    g_scan[N_MAX];       // per-block inclusive scan
__device__ int    g_ptr [N_MAX + 1];   // CSR offsets (by destination)
__device__ int    g_bsum[SCAN_NB];
__device__ int    g_boff[SCAN_NB];
__device__ int2   g_rec [E_MAX];       // sorted-by-dst: {src_row, bits(norm)}
__device__ float4 g_bufA[(size_t)N_MAX * F4];
__device__ float4 g_bufB[(size_t)N_MAX * F4];

// ---- packed f32x2 helpers (FFMA2 is PTX-only on sm_103a) ----------------
__device__ __forceinline__ unsigned long long pack2(float a, float b) {
    unsigned long long r;
    asm("mov.b64 %0, {%1, %2};" : "=l"(r) : "f"(a), "f"(b));
    return r;
}
__device__ __forceinline__ void fma2(unsigned long long& d,
                                     unsigned long long a, unsigned long long b) {
    asm("fma.rn.f32x2 %0, %1, %2, %0;" : "+l"(d) : "l"(a), "l"(b));
}
__device__ __forceinline__ void unpack2(unsigned long long v, float& lo, float& hi) {
    asm("mov.b64 {%0, %1}, %2;" : "=f"(lo), "=f"(hi) : "l"(v));
}

// ---------------------------------------------------------------------------
// 1) init (+ dtype probe in thread 0): int64 probes all land in [0,N);
//    int32 reinterpreted as int64 yields values >= 2^32 (w.h.p.).
__global__ void k_init(const void* __restrict__ ei_raw, int N) {
    int i = blockIdx.x * blockDim.x + threadIdx.x;
    if (i < N) { g_deg[i] = 1.0f; g_cnt[i] = 0; }
    if (i == 0) {
        const long long* p = (const long long*)ei_raw;
        int ok64 = 1;
        for (int k = 0; k < 64; k++) {
            long long v = p[k];
            if (v < 0 || v >= (long long)N) { ok64 = 0; break; }
        }
        g_is64 = ok64;
    }
}

__device__ __forceinline__ int load_idx(const void* ei, size_t pos, int is64, int N) {
    int v = is64 ? (int)((const long long*)ei)[pos]
                 : ((const int*)ei)[pos];
    v = v < 0 ? 0 : (v >= N ? N - 1 : v);   // clamp: never crash
    return v;
}

// 2) decode indices once; accumulate degree + histogram
__global__ void k_prep_edges(const void* __restrict__ ei,
                             const float* __restrict__ w, int E, int N) {
    int e = blockIdx.x * blockDim.x + threadIdx.x;
    if (e < E) {
        int is64 = g_is64;
        int r = load_idx(ei, (size_t)e,     is64, N);
        int c = load_idx(ei, (size_t)E + e, is64, N);
        g_rowi[e] = r;
        g_coli[e] = c;
        atomicAdd(&g_deg[c], w[e]);
        atomicAdd(&g_cnt[c], 1);
    }
}

// ---------------------------------------------------------------------------
// 3) GEMM: z = x @ W^T -> bufA, using packed fma.rn.f32x2 (2 MACs/instr).
//    SMEM holds W transposed: Wt[k][j] so one LDS.128 (= ulonglong2) yields
//    two packed {W[j],W[j+1]} operands. Broadcast across warp -> conflict-free.
//    (Placed as my-launch #3 so ncu's fixed capture slot profiles it.)
__global__ void k_gemm(const float* __restrict__ x,
                       const float* __restrict__ W, int N) {
    __shared__ float Wt[F_IN * F_OUT];   // Wt[k*40 + j] = W[j*256 + k]
    for (int idx = threadIdx.x; idx < F_OUT * F_IN; idx += blockDim.x) {
        int j = idx / F_IN, k = idx - j * F_IN;
        Wt[k * F_OUT + j] = W[idx];
    }
    __syncthreads();

    int n = blockIdx.x * blockDim.x + threadIdx.x;
    if (n >= N) return;

    unsigned long long acc[F_OUT / 2];
#pragma unroll
    for (int j = 0; j < F_OUT / 2; j++) acc[j] = 0ULL;

    const float4* xr = (const float4*)(x + (size_t)n * F_IN);
#pragma unroll 2
    for (int k4 = 0; k4 < F_IN / 4; k4++) {
        float4 xv = xr[k4];
        float xs[4] = {xv.x, xv.y, xv.z, xv.w};
#pragma unroll
        for (int kk = 0; kk < 4; kk++) {
            unsigned long long xx = pack2(xs[kk], xs[kk]);
            const ulonglong2* wrow =
                (const ulonglong2*)&Wt[(k4 * 4 + kk) * F_OUT];
#pragma unroll
            for (int j4 = 0; j4 < F_OUT / 4; j4++) {
                ulonglong2 wp = wrow[j4];      // {W[4j4..4j4+1]},{W[4j4+2..+3]}
                fma2(acc[2 * j4 + 0], xx, wp.x);
                fma2(acc[2 * j4 + 1], xx, wp.y);
            }
        }
    }

    float4* zr = g_bufA + (size_t)n * F4;
#pragma unroll
    for (int c = 0; c < F4; c++) {
        float4 o;
        unpack2(acc[2 * c + 0], o.x, o.y);
        unpack2(acc[2 * c + 1], o.z, o.w);
        zr[c] = o;
    }
}

// ---------------------------------------------------------------------------
// 4a) per-block inclusive scan of cnt
__global__ void k_scanA(int N) {
    __shared__ int s[SCAN_BS];
    int i = blockIdx.x * SCAN_BS + threadIdx.x;
    int v = (i < N) ? g_cnt[i] : 0;
    s[threadIdx.x] = v;
    __syncthreads();
#pragma unroll
    for (int off = 1; off < SCAN_BS; off <<= 1) {
        int t = (threadIdx.x >= off) ? s[threadIdx.x - off] : 0;
        __syncthreads();
        s[threadIdx.x] += t;
        __syncthreads();
    }
    if (i < N) g_scan[i] = s[threadIdx.x];
    if (threadIdx.x == SCAN_BS - 1) g_bsum[blockIdx.x] = s[threadIdx.x];
}

// 4b) serial scan of block sums (98 values)
__global__ void k_scanB(int nb) {
    if (threadIdx.x == 0 && blockIdx.x == 0) {
        int run = 0;
        for (int b = 0; b < nb; b++) { g_boff[b] = run; run += g_bsum[b]; }
    }
}

// 4c) finalize exclusive ptr; zero cursors; dinv (deg final by now)
__global__ void k_scanC(int N) {
    int i = blockIdx.x * blockDim.x + threadIdx.x;
    if (i < N) {
        g_ptr[i + 1] = g_scan[i] + g_boff[i / SCAN_BS];
        g_cur[i] = 0;
        g_dinv[i] = rsqrtf(g_deg[i]);
        if (i == 0) g_ptr[0] = 0;
    }
}

// 5) bucket fill: sorted-by-destination edge records {src, norm}
__global__ void k_fill(const float* __restrict__ w, int E) {
    int e = blockIdx.x * blockDim.x + threadIdx.x;
    if (e < E) {
        int r = g_rowi[e];
        int c = g_coli[e];
        float nrm = g_dinv[r] * w[e] * g_dinv[c];
        int pos = g_ptr[c] + atomicAdd(&g_cur[c], 1);
        g_rec[pos] = make_int2(r, __float_as_int(nrm));
    }
}

// ---------------------------------------------------------------------------
// 6) pull hop: dst[i,:] = dinv[i]^2*src[i,:] + sum_{e: col=i} norm_e*src[row_e,:]
//    5 threads per node, 2 float4 chunks each (32B contiguous per gather):
//    halves the redundant per-node record traffic vs 10 threads/node.
template <bool AtoB>
__global__ void k_hop(int N) {
    int t = blockIdx.x * blockDim.x + threadIdx.x;
    if (t >= N * 5) return;
    const float4* __restrict__ src = AtoB ? g_bufA : g_bufB;
    float4*       __restrict__ dst = AtoB ? g_bufB : g_bufA;

    int node = t / 5;
    int q    = t - node * 5;          // chunk pair index
    int ch   = 2 * q;

    float d  = g_dinv[node];
    float d2 = d * d;
    float4 s0 = src[(size_t)node * F4 + ch];
    float4 s1 = src[(size_t)node * F4 + ch + 1];
    float4 a0 = make_float4(d2 * s0.x, d2 * s0.y, d2 * s0.z, d2 * s0.w);
    float4 a1 = make_float4(d2 * s1.x, d2 * s1.y, d2 * s1.z, d2 * s1.w);

    int beg = g_ptr[node];
    int end = g_ptr[node + 1];
    for (int e = beg; e < end; e++) {
        int2  rec = g_rec[e];
        float nrm = __int_as_float(rec.y);
        const float4* vr = &src[(size_t)rec.x * F4 + ch];
        float4 v0 = vr[0];
        float4 v1 = vr[1];
        a0.x = fmaf(nrm, v0.x, a0.x);  a0.y = fmaf(nrm, v0.y, a0.y);
        a0.z = fmaf(nrm, v0.z, a0.z);  a0.w = fmaf(nrm, v0.w, a0.w);
        a1.x = fmaf(nrm, v1.x, a1.x);  a1.y = fmaf(nrm, v1.y, a1.y);
        a1.z = fmaf(nrm, v1.z, a1.z);  a1.w = fmaf(nrm, v1.w, a1.w);
    }
    dst[(size_t)node * F4 + ch]     = a0;
    dst[(size_t)node * F4 + ch + 1] = a1;
}

// ---------------------------------------------------------------------------
// 7) epilogue: out = log_softmax(relu(h + b))   h = bufA after hop 2
__global__ void k_final(const float* __restrict__ b,
                        float* __restrict__ out, int N) {
    int n = blockIdx.x * blockDim.x + threadIdx.x;
    if (n >= N) return;

    float v[F_OUT];
    const float4* h = g_bufA + (size_t)n * F4;
#pragma unroll
    for (int c = 0; c < F4; c++) {
        float4 t = h[c];
        v[4*c+0] = t.x; v[4*c+1] = t.y; v[4*c+2] = t.z; v[4*c+3] = t.w;
    }
#pragma unroll
    for (int j = 0; j < F_OUT; j++)
        v[j] = fmaxf(v[j] + __ldg(&b[j]), 0.0f);

    float m = -1e30f;
#pragma unroll
    for (int j = 0; j < F_OUT; j++) m = fmaxf(m, v[j]);
    float s = 0.0f;
#pragma unroll
    for (int j = 0; j < F_OUT; j++) s += expf(v[j] - m);
    float lse = m + logf(s);

    float4* o = (float4*)out + (size_t)n * F4;
#pragma unroll
    for (int c = 0; c < F4; c++)
        o[c] = make_float4(v[4*c+0] - lse, v[4*c+1] - lse,
                           v[4*c+2] - lse, v[4*c+3] - lse);
}

// ---------------------------------------------------------------------------
extern "C" void kernel_launch(void* const* d_in, const int* in_sizes, int n_in,
                              void* d_out, int out_size) {
    const float* x   = (const float*)d_in[0];
    const void*  ei  = d_in[1];
    const float* w   = (const float*)d_in[2];
    const float* W   = (const float*)d_in[3];
    const float* b   = (const float*)d_in[4];
    float*       out = (float*)d_out;

    int N = in_sizes[0] / F_IN;   // 100000
    int E = in_sizes[2];          // 1600000

    const int T = 256;
    int gN  = (N + T - 1) / T;
    int gE  = (E + T - 1) / T;
    int gH  = (N * 5 + T - 1) / T;
    int nb  = (N + SCAN_BS - 1) / SCAN_BS;

    // launch order note: ncu's fixed capture slot profiles my launch #3,
    // so GEMM (independent of the CSR build) is placed there.
    k_init      <<<gN, T>>>(ei, N);      // 0: init + dtype probe
    k_prep_edges<<<gE, T>>>(ei, w, E, N);// 1
    k_scanA     <<<nb, SCAN_BS>>>(N);    // 2
    k_gemm      <<<gN, T>>>(x, W, N);    // 3  <- profiled
    k_scanB     <<<1, 32>>>(nb);         // 4
    k_scanC     <<<gN, T>>>(N);          // 5 (ptr + cursors + dinv)
    k_fill      <<<gE, T>>>(w, E);       // 6

    // two atomic-free pull hops
    k_hop<true> <<<gH, T>>>(N);          // 7
    k_hop<false><<<gH, T>>>(N);          // 8

    // epilogue
    k_final<<<gN, T>>>(b, out, N);       // 9
}